// round 11
// baseline (speedup 1.0000x reference)
#include <cuda_runtime.h>
#include <math.h>

#define HH   256
#define WW   256
#define CC   32
#define CVV  64
#define KNN  8
#define NB   2
#define HP   258
#define NPIX (HH*WW)
#define NITER 5
#define NBORD 1028   // border pixels per padded plane: 2*258 + 2*256

// ---------------- scratch (device globals; allocation-free) ----------------
__device__ float    g_qtp[NB*HP*HP*CC];    // q padded, channel-last
__device__ float    g_ktp[NB*HP*HP*CC];    // k padded, channel-last
__device__ float    g_vt [NB*NPIX*CVV];    // v transposed to [b][pix][c]
__device__ float    g_ot [NB*NPIX*CVV];    // output, channel-last staging
__device__ float    g_cost[NB*NPIX*KNN];   // per-pixel sorted candidate costs
__device__ unsigned g_syx [NB*NPIX*KNN];   // packed (sy<<8)|sx
__device__ unsigned g_best[2*NB*NPIX];     // double-buffered best field

struct K2 { unsigned a, b; };
struct InitKeys { K2 ky[NB]; K2 kx[NB]; };            // lower-bits subkeys (span=256)
struct IterKeys { K2 k[NB][2][2][2]; };               // [b][s][dy/dx][hi/lo]

// CTA-local 2D remap: one 512-thread CTA = 16 warps = an 8x2 pixel block.
// L1 reuse is intra-CTA only (consecutive CTAs land on different SMs), so
// the pixels that share patch lines must live in the SAME CTA. Bijection.
__device__ __forceinline__ int warp_to_pix(int w) {
  int u  = w & 15;            // warp within CTA
  int c  = w >> 4;            // CTA within batch (4096)
  int ix = u & 7, iy = u >> 3;           // 8 x 2 block
  int cx = c & 31, cy = c >> 5;          // 32 x 128 blocks
  return ((cy*2 + iy) << 8) | (cx*8 + ix);
}

// ---------------- threefry2x32 (JAX-compatible, partitionable counters) ----
__host__ __device__ __forceinline__ unsigned rotl32(unsigned x, int d) {
  return (x << d) | (x >> (32 - d));
}
__host__ __device__ __forceinline__ void tf2x32(unsigned k0, unsigned k1,
                                                unsigned x0, unsigned x1,
                                                unsigned &o0, unsigned &o1) {
  unsigned ks2 = k0 ^ k1 ^ 0x1BD11BDAu;
  x0 += k0; x1 += k1;
#define TFR(r) { x0 += x1; x1 = rotl32(x1, (r)); x1 ^= x0; }
  TFR(13) TFR(15) TFR(26) TFR(6)   x0 += k1;  x1 += ks2 + 1u;
  TFR(17) TFR(29) TFR(16) TFR(24)  x0 += ks2; x1 += k0  + 2u;
  TFR(13) TFR(15) TFR(26) TFR(6)   x0 += k0;  x1 += k1  + 3u;
  TFR(17) TFR(29) TFR(16) TFR(24)  x0 += k1;  x1 += ks2 + 4u;
  TFR(13) TFR(15) TFR(26) TFR(6)   x0 += ks2; x1 += k0  + 5u;
#undef TFR
  o0 = x0; o1 = x1;
}

// partial (per-lane) patch SSD: no reduction — lets callers batch reductions
__device__ __forceinline__ float patch_partial(int b, const float qv[9],
                                               int sy, int sx, int lane) {
  const float* kp = &g_ktp[(((size_t)b*HP + sy)*HP + sx)*CC + lane];
  float acc = 0.f;
#pragma unroll
  for (int dy = 0; dy < 3; ++dy)
#pragma unroll
    for (int dx = 0; dx < 3; ++dx) {
      float kv = kp[(dy*HP + dx)*CC];
      float d  = qv[dy*3 + dx] - kv;
      acc = fmaf(d, d, acc);
    }
  return acc;
}

// stable insert into sorted-asc 8-list; strict '<' => new loses ties
// (matches XLA top_k stability: lower original index wins on equal values)
__device__ __forceinline__ void ins8(float c[8], unsigned s[8], float xc, unsigned xs) {
  bool lt[8];
#pragma unroll
  for (int i = 0; i < 8; ++i) lt[i] = xc < c[i];
#pragma unroll
  for (int i = 7; i >= 1; --i) {
    c[i] = lt[i-1] ? c[i-1] : (lt[i] ? xc : c[i]);
    s[i] = lt[i-1] ? s[i-1] : (lt[i] ? xs : s[i]);
  }
  if (lt[0]) { c[0] = xc; s[0] = xs; }
}

// ---------------- zero-fill ONLY the padding borders of q/k ----------------
// Border pixel enumeration: [0,258) top row, [258,516) bottom row,
// [516,772) left col rows 1..256, [772,1028) right col rows 1..256.
__global__ __launch_bounds__(256) void zero_qk() {
  int t = blockIdx.x * blockDim.x + threadIdx.x;   // NB*NBORD*CC threads
  if (t >= NB*NBORD*CC) return;
  int ch  = t & 31;
  int bp  = (t >> 5) % NBORD;
  int b   = (t >> 5) / NBORD;
  int y, x;
  if      (bp < 258)  { y = 0;        x = bp; }
  else if (bp < 516)  { y = HP-1;     x = bp - 258; }
  else if (bp < 772)  { y = bp - 515; x = 0; }       // rows 1..256
  else                { y = bp - 771; x = HP-1; }    // rows 1..256
  size_t idx = (((size_t)b*HP + y)*HP + x)*CC + ch;
  g_qtp[idx] = 0.f;
  g_ktp[idx] = 0.f;
}

// ---------------- tiled transpose q,k -> padded channel-last -------------
// Reads coalesced (32 consecutive pixels per channel row), writes coalesced
// (32 consecutive channels = one 128B line per pixel). 32-pixel runs never
// cross an image row (256 % 32 == 0).
__global__ __launch_bounds__(256) void transpose_qk(const float* __restrict__ q,
                                                    const float* __restrict__ k) {
  __shared__ float tq[32][33];
  __shared__ float tk[32][33];
  int b  = blockIdx.z;
  int p0 = blockIdx.x * 32;           // pixel run start
#pragma unroll
  for (int ci = threadIdx.y; ci < 32; ci += 8) {
    size_t src = ((size_t)(b*CC + ci))*NPIX + p0 + threadIdx.x;
    tq[ci][threadIdx.x] = q[src];
    tk[ci][threadIdx.x] = k[src];
  }
  __syncthreads();
#pragma unroll
  for (int i = threadIdx.y; i < 32; i += 8) {
    int p = p0 + i;
    int y = p >> 8, x = p & 255;
    size_t dst = (((size_t)b*HP + y + 1)*HP + (x + 1))*CC + threadIdx.x;
    g_qtp[dst] = tq[threadIdx.x][i];
    g_ktp[dst] = tk[threadIdx.x][i];
  }
}

// ---------------- tiled transpose v -> channel-last ----------------
__global__ __launch_bounds__(256) void transpose_v(const float* __restrict__ v) {
  __shared__ float tile[32][33];
  int b  = blockIdx.z;
  int c0 = blockIdx.y * 32;
  int p0 = blockIdx.x * 32;
#pragma unroll
  for (int i = threadIdx.y; i < 32; i += 8)
    tile[i][threadIdx.x] = v[((size_t)(b*CVV + c0 + i))*NPIX + p0 + threadIdx.x];
  __syncthreads();
#pragma unroll
  for (int i = threadIdx.y; i < 32; i += 8)
    g_vt[((size_t)b*NPIX + p0 + i)*CVV + c0 + threadIdx.x] = tile[threadIdx.x][i];
}

// ---------------- tiled transpose channel-last staging -> planar out -------
__global__ __launch_bounds__(256) void transpose_out(float* __restrict__ out) {
  __shared__ float tile[32][33];
  int b  = blockIdx.z;
  int c0 = blockIdx.y * 32;
  int p0 = blockIdx.x * 32;
#pragma unroll
  for (int i = threadIdx.y; i < 32; i += 8)   // i = pixel, tx = channel
    tile[i][threadIdx.x] = g_ot[((size_t)b*NPIX + p0 + i)*CVV + c0 + threadIdx.x];
  __syncthreads();
#pragma unroll
  for (int i = threadIdx.y; i < 32; i += 8)   // i = channel, tx = pixel
    out[((size_t)(b*CVV + c0 + i))*NPIX + p0 + threadIdx.x] = tile[threadIdx.x][i];
}

// ---------------- init: 8 random candidates, stable sort ----------------
__global__ __launch_bounds__(512) void init_kernel(InitKeys keys) {
  int gw   = (blockIdx.x * blockDim.x + threadIdx.x) >> 5;
  int lane = threadIdx.x & 31;
  int b    = gw >> 16;
  int pix  = warp_to_pix(gw & (NPIX - 1));
  int y = pix >> 8, x = pix & 255;

  // lanes 0..7 -> sy_k, lanes 8..15 -> sx_k.
  // span=256 => randint multiplier is 0, only lower-bits subkey (split[1]) matters.
  unsigned val = 0;
  if (lane < 16) {
    K2 kk = (lane < 8) ? keys.ky[b] : keys.kx[b];
    unsigned i = (unsigned)((lane & 7) * NPIX + pix);
    unsigned o0, o1; tf2x32(kk.a, kk.b, 0u, i, o0, o1);
    val = (o0 ^ o1) & 255u;
  }

  float qv[9];
#pragma unroll
  for (int dy = 0; dy < 3; ++dy)
#pragma unroll
    for (int dx = 0; dx < 3; ++dx)
      qv[dy*3 + dx] = g_qtp[(((size_t)b*HP + y + dy)*HP + x + dx)*CC + lane];

  // phase 1: all 8 partial costs (independent loads -> high MLP)
  unsigned syx[8];
  float pc[8];
#pragma unroll
  for (int kc = 0; kc < 8; ++kc) {
    unsigned sy = __shfl_sync(0xffffffffu, val, kc);
    unsigned sx = __shfl_sync(0xffffffffu, val, kc + 8);
    syx[kc] = (sy << 8) | sx;
    pc[kc] = patch_partial(b, qv, (int)sy, (int)sx, lane);
  }
  // phase 2: joint butterfly reductions (8 independent SHFLs per step)
#pragma unroll
  for (int o = 16; o > 0; o >>= 1)
#pragma unroll
    for (int kc = 0; kc < 8; ++kc)
      pc[kc] += __shfl_xor_sync(0xffffffffu, pc[kc], o);

  // phase 3: stable sort via insertion
  float c[8]; unsigned s[8];
#pragma unroll
  for (int i = 0; i < 8; ++i) { c[i] = __int_as_float(0x7f800000); s[i] = 0u; }
#pragma unroll
  for (int kc = 0; kc < 8; ++kc)
    ins8(c, s, pc[kc], syx[kc]);

  if (lane == 0) {
    size_t base = ((size_t)b*NPIX + pix)*KNN;
    float4*   oc = (float4*)&g_cost[base];
    uint4*    os = (uint4*) &g_syx [base];
    oc[0] = make_float4(c[0], c[1], c[2], c[3]);
    oc[1] = make_float4(c[4], c[5], c[6], c[7]);
    os[0] = make_uint4(s[0], s[1], s[2], s[3]);
    os[1] = make_uint4(s[4], s[5], s[6], s[7]);
    g_best[0*NB*NPIX + b*NPIX + pix] = s[0];
  }
}

// ---------------- one PatchMatch iteration (optionally fused epilogue) -----
__global__ __launch_bounds__(512) void iter_kernel(IterKeys keys, int inbuf, int last) {
  int gw   = (blockIdx.x * blockDim.x + threadIdx.x) >> 5;
  int lane = threadIdx.x & 31;
  int b    = gw >> 16;
  int pix  = warp_to_pix(gw & (NPIX - 1));
  int y = pix >> 8, x = pix & 255;

  // --- issue all independent memory early: prior list, best field, q patch ---
  size_t base = ((size_t)b*NPIX + pix)*KNN;
  float4 pc0 = ((const float4*)&g_cost[base])[0];
  float4 pc1 = ((const float4*)&g_cost[base])[1];
  uint4  ps0 = ((const uint4*) &g_syx [base])[0];
  uint4  ps1 = ((const uint4*) &g_syx [base])[1];

  const unsigned* bestin = &g_best[inbuf*NB*NPIX + b*NPIX];
  unsigned bl = bestin[y*WW + ((x + WW - 1) & (WW - 1))];
  unsigned br = bestin[y*WW + ((x + 1)      & (WW - 1))];
  unsigned bu = bestin[((y + HH - 1) & (HH - 1))*WW + x];
  unsigned bd = bestin[((y + 1)      & (HH - 1))*WW + x];
  unsigned bc = bestin[pix];

  float qv[9];
#pragma unroll
  for (int dy = 0; dy < 3; ++dy)
#pragma unroll
    for (int dx = 0; dx < 3; ++dx)
      qv[dy*3 + dx] = g_qtp[(((size_t)b*HP + y + dy)*HP + x + dx)*CC + lane];

  // --- threefry (ALU) overlaps the loads above ---
  unsigned bits = 0;
  if (lane < 8) {
    K2 kk = keys.k[b][lane >> 2][(lane >> 1) & 1][lane & 1];
    unsigned o0, o1; tf2x32(kk.a, kk.b, 0u, (unsigned)pix, o0, o1);
    bits = o0 ^ o1;
  }
  unsigned h0 = __shfl_sync(0xffffffffu, bits, 0), l0 = __shfl_sync(0xffffffffu, bits, 1);
  unsigned h1 = __shfl_sync(0xffffffffu, bits, 2), l1 = __shfl_sync(0xffffffffu, bits, 3);
  unsigned h2 = __shfl_sync(0xffffffffu, bits, 4), l2 = __shfl_sync(0xffffffffu, bits, 5);
  unsigned h3 = __shfl_sync(0xffffffffu, bits, 6), l3 = __shfl_sync(0xffffffffu, bits, 7);
  // randint double-draw: span 257 (rad 128) mult=1 ; span 129 (rad 64) mult=16
  int dy0 = (int)(((h0 % 257u) * 1u  + (l0 % 257u)) % 257u) - 128;
  int dx0 = (int)(((h1 % 257u) * 1u  + (l1 % 257u)) % 257u) - 128;
  int dy1 = (int)(((h2 % 129u) * 16u + (l2 % 129u)) % 129u) - 64;
  int dx1 = (int)(((h3 % 129u) * 16u + (l3 % 129u)) % 129u) - 64;

  int bcy = (int)(bc >> 8), bcx = (int)(bc & 255u);
  int cy[6] = { (int)(bl >> 8),        (int)(br >> 8),
                (int)(bu >> 8) + 1,    (int)(bd >> 8) - 1,
                bcy + dy0,             bcy + dy1 };
  int cx[6] = { (int)(bl & 255u) + 1,  (int)(br & 255u) - 1,
                (int)(bu & 255u),      (int)(bd & 255u),
                bcx + dx0,             bcx + dx1 };

  // phase 1: 6 partial costs (54 independent gather loads -> high MLP)
  unsigned nsyx[6];
  float pc6[6];
#pragma unroll
  for (int j = 0; j < 6; ++j) {
    int sy = cy[j]; sy = sy < 0 ? 0 : (sy > 255 ? 255 : sy);
    int sx = cx[j]; sx = sx < 0 ? 0 : (sx > 255 ? 255 : sx);
    nsyx[j] = (unsigned)((sy << 8) | sx);
    pc6[j] = patch_partial(b, qv, sy, sx, lane);
  }
  // phase 2: joint butterfly reductions
#pragma unroll
  for (int o = 16; o > 0; o >>= 1)
#pragma unroll
    for (int j = 0; j < 6; ++j)
      pc6[j] += __shfl_xor_sync(0xffffffffu, pc6[j], o);

  // phase 3: merge into prior sorted list (all lanes hold identical lists)
  float c[8]; unsigned s[8];
  c[0]=pc0.x; c[1]=pc0.y; c[2]=pc0.z; c[3]=pc0.w;
  c[4]=pc1.x; c[5]=pc1.y; c[6]=pc1.z; c[7]=pc1.w;
  s[0]=ps0.x; s[1]=ps0.y; s[2]=ps0.z; s[3]=ps0.w;
  s[4]=ps1.x; s[5]=ps1.y; s[6]=ps1.z; s[7]=ps1.w;
#pragma unroll
  for (int j = 0; j < 6; ++j)
    ins8(c, s, pc6[j], nsyx[j]);

  if (!last) {
    if (lane == 0) {
      float4* oc = (float4*)&g_cost[base];
      uint4*  os = (uint4*) &g_syx [base];
      oc[0] = make_float4(c[0], c[1], c[2], c[3]);
      oc[1] = make_float4(c[4], c[5], c[6], c[7]);
      os[0] = make_uint4(s[0], s[1], s[2], s[3]);
      os[1] = make_uint4(s[4], s[5], s[6], s[7]);
      g_best[(1 - inbuf)*NB*NPIX + b*NPIX + pix] = s[0];
    }
    return;
  }

  // --- fused epilogue: softmax over -cost, weighted gather of v ----------
  float e[8];
  e[0] = 1.f;                               // expf(c[0]-c[0]); c[0] = min
#pragma unroll
  for (int i = 1; i < 8; ++i) e[i] = expf(c[0] - c[i]);
  float sum = e[0]+e[1]+e[2]+e[3]+e[4]+e[5]+e[6]+e[7];
  float inv = 1.f / sum;

  const float* vt = &g_vt[(size_t)b*NPIX*CVV];
  float a0 = 0.f, a1 = 0.f;
#pragma unroll
  for (int kc = 0; kc < 8; ++kc) {
    const float* p = &vt[(size_t)s[kc]*CVV];   // packed syx == flat pix index
    float w = e[kc] * inv;
    a0 = fmaf(w, p[lane],      a0);
    a1 = fmaf(w, p[lane + 32], a1);
  }
  // channel-last staging: two coalesced 128B lines per warp
  float* ot = &g_ot[((size_t)b*NPIX + pix)*CVV];
  ot[lane]      = a0;
  ot[lane + 32] = a1;
}

// ---------------- host: key schedule + launches ----------------
extern "C" void kernel_launch(void* const* d_in, const int* in_sizes, int n_in,
                              void* d_out, int out_size) {
  const float* q = (const float*)d_in[0];
  const float* k = (const float*)d_in[1];
  const float* v = (const float*)d_in[2];
  float* out = (float*)d_out;

  // JAX threefry key schedule (partitionable counters), computed at capture time.
  unsigned kb[NB][2];
  for (int b = 0; b < NB; ++b)
    tf2x32(0u, 42u, 0u, (unsigned)b, kb[b][0], kb[b][1]);   // split(key(42), 2)

  InitKeys ik;
  IterKeys itks[NITER];
  for (int b = 0; b < NB; ++b) {
    unsigned t0, t1;
    // randint span=256: multiplier==0 -> only lower-bits subkey split[1] used
    tf2x32(kb[b][0], kb[b][1], 0u, 10000u, t0, t1);
    tf2x32(t0, t1, 0u, 1u, ik.ky[b].a, ik.ky[b].b);
    tf2x32(kb[b][0], kb[b][1], 0u, 10001u, t0, t1);
    tf2x32(t0, t1, 0u, 1u, ik.kx[b].a, ik.kx[b].b);
    for (int it = 0; it < NITER; ++it) {
      unsigned ki0, ki1;
      tf2x32(kb[b][0], kb[b][1], 0u, (unsigned)it, ki0, ki1);   // fold_in(key, it)
      for (int s = 0; s < 2; ++s) {
        unsigned kd0, kd1;
        tf2x32(ki0, ki1, 0u, (unsigned)(2*s), kd0, kd1);        // dy key
        tf2x32(kd0, kd1, 0u, 0u, itks[it].k[b][s][0][0].a, itks[it].k[b][s][0][0].b);
        tf2x32(kd0, kd1, 0u, 1u, itks[it].k[b][s][0][1].a, itks[it].k[b][s][0][1].b);
        tf2x32(ki0, ki1, 0u, (unsigned)(2*s + 1), kd0, kd1);    // dx key
        tf2x32(kd0, kd1, 0u, 0u, itks[it].k[b][s][1][0].a, itks[it].k[b][s][1][0].b);
        tf2x32(kd0, kd1, 0u, 1u, itks[it].k[b][s][1][1].a, itks[it].k[b][s][1][1].b);
      }
    }
  }

  zero_qk<<<(NB*NBORD*CC + 255)/256, 256>>>();
  {
    dim3 tb(32, 8, 1);
    dim3 tg(NPIX/32, 1, NB);
    transpose_qk<<<tg, tb>>>(q, k);
  }
  {
    dim3 tb(32, 8, 1);
    dim3 tg(NPIX/32, CVV/32, NB);
    transpose_v<<<tg, tb>>>(v);
  }
  init_kernel<<<(NB*NPIX)/16, 512>>>(ik);
  int inbuf = 0;
  for (int it = 0; it < NITER; ++it) {
    iter_kernel<<<(NB*NPIX)/16, 512>>>(itks[it], inbuf, it == NITER - 1 ? 1 : 0);
    inbuf ^= 1;
  }
  {
    dim3 tb(32, 8, 1);
    dim3 tg(NPIX/32, CVV/32, NB);
    transpose_out<<<tg, tb>>>(out);
  }
}

// round 15
// speedup vs baseline: 1.4639x; 1.4639x over previous
#include <cuda_runtime.h>
#include <math.h>

#define HH   256
#define WW   256
#define CC   32
#define CVV  64
#define KNN  8
#define NB   2
#define HP   258
#define NPIX (HH*WW)
#define NITER 5
#define NBORD 1028   // border pixels per padded plane: 2*258 + 2*256

// ---------------- scratch (device globals; allocation-free) ----------------
__device__ float    g_qtp[NB*HP*HP*CC];    // q padded, channel-last
__device__ float    g_ktp[NB*HP*HP*CC];    // k padded, channel-last
__device__ float    g_vt [NB*NPIX*CVV];    // v transposed to [b][pix][c]
__device__ float    g_ot [NB*NPIX*CVV];    // output, channel-last staging
__device__ float    g_cost[NB*NPIX*KNN];   // per-pixel sorted candidate costs
__device__ unsigned g_syx [NB*NPIX*KNN];   // packed (sy<<8)|sx
__device__ unsigned g_best[2*NB*NPIX];     // double-buffered best field

struct K2 { unsigned a, b; };
struct InitKeys { K2 ky[NB]; K2 kx[NB]; };            // lower-bits subkeys (span=256)
struct IterKeys { K2 k[NB][2][2][2]; };               // [b][s][dy/dx][hi/lo]

// ---------------- threefry2x32 (JAX-compatible, partitionable counters) ----
__host__ __device__ __forceinline__ unsigned rotl32(unsigned x, int d) {
  return (x << d) | (x >> (32 - d));
}
__host__ __device__ __forceinline__ void tf2x32(unsigned k0, unsigned k1,
                                                unsigned x0, unsigned x1,
                                                unsigned &o0, unsigned &o1) {
  unsigned ks2 = k0 ^ k1 ^ 0x1BD11BDAu;
  x0 += k0; x1 += k1;
#define TFR(r) { x0 += x1; x1 = rotl32(x1, (r)); x1 ^= x0; }
  TFR(13) TFR(15) TFR(26) TFR(6)   x0 += k1;  x1 += ks2 + 1u;
  TFR(17) TFR(29) TFR(16) TFR(24)  x0 += ks2; x1 += k0  + 2u;
  TFR(13) TFR(15) TFR(26) TFR(6)   x0 += k0;  x1 += k1  + 3u;
  TFR(17) TFR(29) TFR(16) TFR(24)  x0 += k1;  x1 += ks2 + 4u;
  TFR(13) TFR(15) TFR(26) TFR(6)   x0 += ks2; x1 += k0  + 5u;
#undef TFR
  o0 = x0; o1 = x1;
}

// per-lane (2-channel) patch SSD partial; caller reduces over the 16-lane half
__device__ __forceinline__ float patch_partial2(const float2* __restrict__ kbase,
                                                const float2 qv[9],
                                                int sy, int sx, int sub) {
  const float2* kp = kbase + (unsigned)(sy*HP + sx)*16u + sub;
  float ax = 0.f, ay = 0.f;
#pragma unroll
  for (int dy = 0; dy < 3; ++dy)
#pragma unroll
    for (int dx = 0; dx < 3; ++dx) {
      float2 kv = kp[(dy*HP + dx)*16];
      float dxx = qv[dy*3 + dx].x - kv.x;
      float dyy = qv[dy*3 + dx].y - kv.y;
      ax = fmaf(dxx, dxx, ax);
      ay = fmaf(dyy, dyy, ay);
    }
  return ax + ay;
}

// stable insert into sorted-asc 8-list; strict '<' => new loses ties
// (matches XLA top_k stability: lower original index wins on equal values)
__device__ __forceinline__ void ins8(float c[8], unsigned s[8], float xc, unsigned xs) {
  bool lt[8];
#pragma unroll
  for (int i = 0; i < 8; ++i) lt[i] = xc < c[i];
#pragma unroll
  for (int i = 7; i >= 1; --i) {
    c[i] = lt[i-1] ? c[i-1] : (lt[i] ? xc : c[i]);
    s[i] = lt[i-1] ? s[i-1] : (lt[i] ? xs : s[i]);
  }
  if (lt[0]) { c[0] = xc; s[0] = xs; }
}

// ---------------- zero-fill ONLY the padding borders of q/k ----------------
__global__ __launch_bounds__(256) void zero_qk() {
  int t = blockIdx.x * blockDim.x + threadIdx.x;   // NB*NBORD*CC threads
  if (t >= NB*NBORD*CC) return;
  int ch  = t & 31;
  int bp  = (t >> 5) % NBORD;
  int b   = (t >> 5) / NBORD;
  int y, x;
  if      (bp < 258)  { y = 0;        x = bp; }
  else if (bp < 516)  { y = HP-1;     x = bp - 258; }
  else if (bp < 772)  { y = bp - 515; x = 0; }       // rows 1..256
  else                { y = bp - 771; x = HP-1; }    // rows 1..256
  unsigned idx = ((unsigned)(b*HP + y)*HP + x)*CC + ch;
  g_qtp[idx] = 0.f;
  g_ktp[idx] = 0.f;
}

// ---------------- tiled transpose q,k -> padded channel-last -------------
__global__ __launch_bounds__(256) void transpose_qk(const float* __restrict__ q,
                                                    const float* __restrict__ k) {
  __shared__ float tq[32][33];
  __shared__ float tk[32][33];
  int b  = blockIdx.z;
  int p0 = blockIdx.x * 32;           // pixel run start
#pragma unroll
  for (int ci = threadIdx.y; ci < 32; ci += 8) {
    unsigned src = (unsigned)(b*CC + ci)*NPIX + p0 + threadIdx.x;
    tq[ci][threadIdx.x] = q[src];
    tk[ci][threadIdx.x] = k[src];
  }
  __syncthreads();
#pragma unroll
  for (int i = threadIdx.y; i < 32; i += 8) {
    int p = p0 + i;
    int y = p >> 8, x = p & 255;
    unsigned dst = ((unsigned)(b*HP + y + 1)*HP + (x + 1))*CC + threadIdx.x;
    g_qtp[dst] = tq[threadIdx.x][i];
    g_ktp[dst] = tk[threadIdx.x][i];
  }
}

// ---------------- tiled transpose v -> channel-last ----------------
__global__ __launch_bounds__(256) void transpose_v(const float* __restrict__ v) {
  __shared__ float tile[32][33];
  int b  = blockIdx.z;
  int c0 = blockIdx.y * 32;
  int p0 = blockIdx.x * 32;
#pragma unroll
  for (int i = threadIdx.y; i < 32; i += 8)
    tile[i][threadIdx.x] = v[(unsigned)(b*CVV + c0 + i)*NPIX + p0 + threadIdx.x];
  __syncthreads();
#pragma unroll
  for (int i = threadIdx.y; i < 32; i += 8)
    g_vt[(unsigned)(b*NPIX + p0 + i)*CVV + c0 + threadIdx.x] = tile[threadIdx.x][i];
}

// ---------------- tiled transpose channel-last staging -> planar out -------
__global__ __launch_bounds__(256) void transpose_out(float* __restrict__ out) {
  __shared__ float tile[32][33];
  int b  = blockIdx.z;
  int c0 = blockIdx.y * 32;
  int p0 = blockIdx.x * 32;
#pragma unroll
  for (int i = threadIdx.y; i < 32; i += 8)   // i = pixel, tx = channel
    tile[i][threadIdx.x] = g_ot[(unsigned)(b*NPIX + p0 + i)*CVV + c0 + threadIdx.x];
  __syncthreads();
#pragma unroll
  for (int i = threadIdx.y; i < 32; i += 8)   // i = channel, tx = pixel
    out[(unsigned)(b*CVV + c0 + i)*NPIX + p0 + threadIdx.x] = tile[threadIdx.x][i];
}

// ============ 2-pixels-per-warp layout ============
// half h = lane>>4 (pixel within warp), sub = lane&15 (2 channels: 2*sub, 2*sub+1)
// 256-thread CTA = 8 warps = 16 pixels as an 8x2 block (CTA-local L1 reuse).
__device__ __forceinline__ int pair_pix(int w, int h) {
  int u  = w & 7;             // warp within CTA
  int c  = w >> 3;            // CTA within batch (4096)
  int ix = (u & 3)*2 + h;     // 8 wide
  int iy = u >> 2;            // 2 tall
  int cx = c & 31, cy = c >> 5;   // 32 x 128 CTAs
  return ((cy*2 + iy) << 8) | (cx*8 + ix);
}

// ---------------- init: 8 random candidates, stable sort ----------------
__global__ __launch_bounds__(256) void init_kernel(InitKeys keys) {
  int gw   = blockIdx.x * 8 + (threadIdx.x >> 5);
  int lane = threadIdx.x & 31;
  int h    = lane >> 4;
  int sub  = lane & 15;
  int b    = gw >> 15;                 // NPIX/2 pixel-pairs per batch
  int w    = gw & 32767;
  int pix  = pair_pix(w, h);
  int y = pix >> 8, x = pix & 255;

  // draws: per half, sub 0..7 -> sy_j, sub 8..15 -> sx_j (span=256 -> low bits)
  K2 kk = (sub < 8) ? keys.ky[b] : keys.kx[b];
  unsigned i = (unsigned)((sub & 7) * NPIX + pix);
  unsigned o0, o1; tf2x32(kk.a, kk.b, 0u, i, o0, o1);
  unsigned val = (o0 ^ o1) & 255u;

  const float2* qbase = (const float2*)g_qtp + (unsigned)b*(HP*HP*16u);
  const float2* kbase = (const float2*)g_ktp + (unsigned)b*(HP*HP*16u);
  float2 qv[9];
#pragma unroll
  for (int dy = 0; dy < 3; ++dy)
#pragma unroll
    for (int dx = 0; dx < 3; ++dx)
      qv[dy*3 + dx] = qbase[(unsigned)((y + dy)*HP + (x + dx))*16u + sub];

  // phase 1: 8 partial costs
  unsigned syx[8];
  float pc[8];
#pragma unroll
  for (int kc = 0; kc < 8; ++kc) {
    unsigned sy = __shfl_sync(0xffffffffu, val, (lane & 16) + kc);
    unsigned sx = __shfl_sync(0xffffffffu, val, (lane & 16) + 8 + kc);
    syx[kc] = (sy << 8) | sx;
    pc[kc] = patch_partial2(kbase, qv, (int)sy, (int)sx, sub);
  }
  // phase 2: joint butterfly over the 16-lane half
#pragma unroll
  for (int o = 8; o > 0; o >>= 1)
#pragma unroll
    for (int kc = 0; kc < 8; ++kc)
      pc[kc] += __shfl_xor_sync(0xffffffffu, pc[kc], o);

  // phase 3: stable sort via insertion
  float c[8]; unsigned s[8];
#pragma unroll
  for (int j = 0; j < 8; ++j) { c[j] = __int_as_float(0x7f800000); s[j] = 0u; }
#pragma unroll
  for (int kc = 0; kc < 8; ++kc)
    ins8(c, s, pc[kc], syx[kc]);

  if (sub == 0) {
    unsigned base = (unsigned)(b*NPIX + pix)*KNN;
    float4*   oc = (float4*)&g_cost[base];
    uint4*    os = (uint4*) &g_syx [base];
    oc[0] = make_float4(c[0], c[1], c[2], c[3]);
    oc[1] = make_float4(c[4], c[5], c[6], c[7]);
    os[0] = make_uint4(s[0], s[1], s[2], s[3]);
    os[1] = make_uint4(s[4], s[5], s[6], s[7]);
    g_best[0*NB*NPIX + b*NPIX + pix] = s[0];
  }
}

// ---------------- one PatchMatch iteration (optionally fused epilogue) -----
__global__ __launch_bounds__(256) void iter_kernel(IterKeys keys, int inbuf, int last) {
  int gw   = blockIdx.x * 8 + (threadIdx.x >> 5);
  int lane = threadIdx.x & 31;
  int h    = lane >> 4;
  int sub  = lane & 15;
  int b    = gw >> 15;
  int w    = gw & 32767;
  int pix  = pair_pix(w, h);
  int y = pix >> 8, x = pix & 255;

  // --- issue independent memory early: prior list, best field, q patch ---
  unsigned base = (unsigned)(b*NPIX + pix)*KNN;
  float4 pc0 = ((const float4*)&g_cost[base])[0];
  float4 pc1 = ((const float4*)&g_cost[base])[1];
  uint4  ps0 = ((const uint4*) &g_syx [base])[0];
  uint4  ps1 = ((const uint4*) &g_syx [base])[1];

  const unsigned* bestin = &g_best[inbuf*NB*NPIX + b*NPIX];
  unsigned bl = bestin[y*WW + ((x + WW - 1) & (WW - 1))];
  unsigned br = bestin[y*WW + ((x + 1)      & (WW - 1))];
  unsigned bu = bestin[((y + HH - 1) & (HH - 1))*WW + x];
  unsigned bd = bestin[((y + 1)      & (HH - 1))*WW + x];
  unsigned bc = bestin[pix];

  const float2* qbase = (const float2*)g_qtp + (unsigned)b*(HP*HP*16u);
  const float2* kbase = (const float2*)g_ktp + (unsigned)b*(HP*HP*16u);
  float2 qv[9];
#pragma unroll
  for (int dy = 0; dy < 3; ++dy)
#pragma unroll
    for (int dx = 0; dx < 3; ++dx)
      qv[dy*3 + dx] = qbase[(unsigned)((y + dy)*HP + (x + dx))*16u + sub];

  // --- threefry (ALU) overlaps loads: sub 0..7 of each half computes draws ---
  unsigned bits = 0;
  if (sub < 8) {
    K2 kk = keys.k[b][sub >> 2][(sub >> 1) & 1][sub & 1];
    unsigned o0, o1; tf2x32(kk.a, kk.b, 0u, (unsigned)pix, o0, o1);
    bits = o0 ^ o1;
  }
  int hb = lane & 16;
  unsigned h0 = __shfl_sync(0xffffffffu, bits, hb + 0), l0 = __shfl_sync(0xffffffffu, bits, hb + 1);
  unsigned h1 = __shfl_sync(0xffffffffu, bits, hb + 2), l1 = __shfl_sync(0xffffffffu, bits, hb + 3);
  unsigned h2 = __shfl_sync(0xffffffffu, bits, hb + 4), l2 = __shfl_sync(0xffffffffu, bits, hb + 5);
  unsigned h3 = __shfl_sync(0xffffffffu, bits, hb + 6), l3 = __shfl_sync(0xffffffffu, bits, hb + 7);
  // randint double-draw: span 257 (rad 128) mult=1 ; span 129 (rad 64) mult=16
  int dy0 = (int)(((h0 % 257u) * 1u  + (l0 % 257u)) % 257u) - 128;
  int dx0 = (int)(((h1 % 257u) * 1u  + (l1 % 257u)) % 257u) - 128;
  int dy1 = (int)(((h2 % 129u) * 16u + (l2 % 129u)) % 129u) - 64;
  int dx1 = (int)(((h3 % 129u) * 16u + (l3 % 129u)) % 129u) - 64;

  int bcy = (int)(bc >> 8), bcx = (int)(bc & 255u);
  int cy[6] = { (int)(bl >> 8),        (int)(br >> 8),
                (int)(bu >> 8) + 1,    (int)(bd >> 8) - 1,
                bcy + dy0,             bcy + dy1 };
  int cx[6] = { (int)(bl & 255u) + 1,  (int)(br & 255u) - 1,
                (int)(bu & 255u),      (int)(bd & 255u),
                bcx + dx0,             bcx + dx1 };

  // phase 1: 6 partial costs
  unsigned nsyx[6];
  float pc6[6];
#pragma unroll
  for (int j = 0; j < 6; ++j) {
    int sy = cy[j]; sy = sy < 0 ? 0 : (sy > 255 ? 255 : sy);
    int sx = cx[j]; sx = sx < 0 ? 0 : (sx > 255 ? 255 : sx);
    nsyx[j] = (unsigned)((sy << 8) | sx);
    pc6[j] = patch_partial2(kbase, qv, sy, sx, sub);
  }
  // phase 2: joint butterfly over the 16-lane half
#pragma unroll
  for (int o = 8; o > 0; o >>= 1)
#pragma unroll
    for (int j = 0; j < 6; ++j)
      pc6[j] += __shfl_xor_sync(0xffffffffu, pc6[j], o);

  // phase 3: merge into prior sorted list (uniform within each half)
  float c[8]; unsigned s[8];
  c[0]=pc0.x; c[1]=pc0.y; c[2]=pc0.z; c[3]=pc0.w;
  c[4]=pc1.x; c[5]=pc1.y; c[6]=pc1.z; c[7]=pc1.w;
  s[0]=ps0.x; s[1]=ps0.y; s[2]=ps0.z; s[3]=ps0.w;
  s[4]=ps1.x; s[5]=ps1.y; s[6]=ps1.z; s[7]=ps1.w;
#pragma unroll
  for (int j = 0; j < 6; ++j)
    ins8(c, s, pc6[j], nsyx[j]);

  if (!last) {
    if (sub == 0) {
      float4* oc = (float4*)&g_cost[base];
      uint4*  os = (uint4*) &g_syx [base];
      oc[0] = make_float4(c[0], c[1], c[2], c[3]);
      oc[1] = make_float4(c[4], c[5], c[6], c[7]);
      os[0] = make_uint4(s[0], s[1], s[2], s[3]);
      os[1] = make_uint4(s[4], s[5], s[6], s[7]);
      g_best[(1 - inbuf)*NB*NPIX + b*NPIX + pix] = s[0];
    }
    return;
  }

  // --- fused epilogue: softmax over -cost, weighted gather of v ----------
  float e[8];
  e[0] = 1.f;                               // expf(c[0]-c[0]); c[0] = min
#pragma unroll
  for (int j = 1; j < 8; ++j) e[j] = expf(c[0] - c[j]);
  float sum = e[0]+e[1]+e[2]+e[3]+e[4]+e[5]+e[6]+e[7];
  float inv = 1.f / sum;

  const float2* vt2 = (const float2*)g_vt + (unsigned)b*(NPIX*32u);
  float2 a0 = make_float2(0.f, 0.f), a1 = make_float2(0.f, 0.f);
#pragma unroll
  for (int kc = 0; kc < 8; ++kc) {
    const float2* p = vt2 + (unsigned)s[kc]*32u;    // packed syx == flat pix index
    float2 v0 = p[sub];        // channels 2*sub, 2*sub+1
    float2 v1 = p[sub + 16];   // channels 32+2*sub, 33+2*sub
    float wgt = e[kc] * inv;
    a0.x = fmaf(wgt, v0.x, a0.x); a0.y = fmaf(wgt, v0.y, a0.y);
    a1.x = fmaf(wgt, v1.x, a1.x); a1.y = fmaf(wgt, v1.y, a1.y);
  }
  float2* ot2 = (float2*)g_ot + (unsigned)(b*NPIX + pix)*32u;
  ot2[sub]      = a0;
  ot2[sub + 16] = a1;
}

// ---------------- host: key schedule + launches ----------------
extern "C" void kernel_launch(void* const* d_in, const int* in_sizes, int n_in,
                              void* d_out, int out_size) {
  const float* q = (const float*)d_in[0];
  const float* k = (const float*)d_in[1];
  const float* v = (const float*)d_in[2];
  float* out = (float*)d_out;

  // JAX threefry key schedule (partitionable counters), computed at capture time.
  unsigned kb[NB][2];
  for (int b = 0; b < NB; ++b)
    tf2x32(0u, 42u, 0u, (unsigned)b, kb[b][0], kb[b][1]);   // split(key(42), 2)

  InitKeys ik;
  IterKeys itks[NITER];
  for (int b = 0; b < NB; ++b) {
    unsigned t0, t1;
    // randint span=256: multiplier==0 -> only lower-bits subkey split[1] used
    tf2x32(kb[b][0], kb[b][1], 0u, 10000u, t0, t1);
    tf2x32(t0, t1, 0u, 1u, ik.ky[b].a, ik.ky[b].b);
    tf2x32(kb[b][0], kb[b][1], 0u, 10001u, t0, t1);
    tf2x32(t0, t1, 0u, 1u, ik.kx[b].a, ik.kx[b].b);
    for (int it = 0; it < NITER; ++it) {
      unsigned ki0, ki1;
      tf2x32(kb[b][0], kb[b][1], 0u, (unsigned)it, ki0, ki1);   // fold_in(key, it)
      for (int s = 0; s < 2; ++s) {
        unsigned kd0, kd1;
        tf2x32(ki0, ki1, 0u, (unsigned)(2*s), kd0, kd1);        // dy key
        tf2x32(kd0, kd1, 0u, 0u, itks[it].k[b][s][0][0].a, itks[it].k[b][s][0][0].b);
        tf2x32(kd0, kd1, 0u, 1u, itks[it].k[b][s][0][1].a, itks[it].k[b][s][0][1].b);
        tf2x32(ki0, ki1, 0u, (unsigned)(2*s + 1), kd0, kd1);    // dx key
        tf2x32(kd0, kd1, 0u, 0u, itks[it].k[b][s][1][0].a, itks[it].k[b][s][1][0].b);
        tf2x32(kd0, kd1, 0u, 1u, itks[it].k[b][s][1][1].a, itks[it].k[b][s][1][1].b);
      }
    }
  }

  zero_qk<<<(NB*NBORD*CC + 255)/256, 256>>>();
  {
    dim3 tb(32, 8, 1);
    dim3 tg(NPIX/32, 1, NB);
    transpose_qk<<<tg, tb>>>(q, k);
  }
  {
    dim3 tb(32, 8, 1);
    dim3 tg(NPIX/32, CVV/32, NB);
    transpose_v<<<tg, tb>>>(v);
  }
  // 2 pixels per warp: NB*NPIX/2 warps, 8 warps per 256-thread CTA
  init_kernel<<<(NB*NPIX/2)/8, 256>>>(ik);
  int inbuf = 0;
  for (int it = 0; it < NITER; ++it) {
    iter_kernel<<<(NB*NPIX/2)/8, 256>>>(itks[it], inbuf, it == NITER - 1 ? 1 : 0);
    inbuf ^= 1;
  }
  {
    dim3 tb(32, 8, 1);
    dim3 tg(NPIX/32, CVV/32, NB);
    transpose_out<<<tg, tb>>>(out);
  }
}